// round 12
// baseline (speedup 1.0000x reference)
#include <cuda_runtime.h>

// Problem constants
#define BB   32
#define NN   2048
#define DD   65
#define HH   64
#define DSQ  (DD*DD)        // 4225
#define GSUB 64             // gram sub-tile rows
#define GNS  2              // sub-tiles per gram block
#define GCH  (GSUB*GNS)     // 128 rows per gram block
#define NGC  (NN/GCH)       // 16 partials per batch
#define OCH  128            // out chunk rows
#define NOC  (NN/OCH)       // 16

typedef unsigned long long ull;

// Scratch (no allocations allowed)
__device__ float g_Gpart[BB * NGC * DSQ];   // partial Gram matrices (~8.6 MB)
__device__ float g_M[BB * DSQ];             // M = A * G * Wv^T per batch

// ---- packed fp32x2 helpers ----
__device__ __forceinline__ ull pack2(float x) {
    ull d; unsigned u = __float_as_uint(x);
    asm("mov.b64 %0, {%1, %1};" : "=l"(d) : "r"(u));
    return d;
}
__device__ __forceinline__ ull fma2(ull a, ull b, ull c) {
    ull d;
    asm("fma.rn.f32x2 %0, %1, %2, %3;" : "=l"(d) : "l"(a), "l"(b), "l"(c));
    return d;
}
__device__ __forceinline__ void unpack2(ull d, float& lo, float& hi) {
    unsigned a, b;
    asm("mov.b64 {%0, %1}, %2;" : "=r"(a), "=r"(b) : "l"(d));
    lo = __uint_as_float(a); hi = __uint_as_float(b);
}

// ---------------------------------------------------------------------------
// Kernel 1: partial Gram, 128 rows / block as 2 x 64-row smem tiles. (R8, proven)
// ---------------------------------------------------------------------------
__global__ void __launch_bounds__(256, 4) k_gram(const float* __restrict__ x) {
    __shared__ __align__(16) float xs[GSUB * 68 + 16];

    const int b = blockIdx.y, c = blockIdx.x;
    const int tid = threadIdx.x;
    const int ty = tid >> 4, tx = tid & 15;
    const int p0 = tx, p1 = 16 + tx, p2 = (tx == 0) ? 32 : 33;

    int iv[5];
#pragma unroll
    for (int u = 0; u < 5; ++u) {
        int i = ty + 16 * u;
        iv[u] = (i < DD) ? i : (DD - 1);
    }

    ull acc[5][3];
#pragma unroll
    for (int u = 0; u < 5; ++u)
#pragma unroll
        for (int v = 0; v < 3; ++v) acc[u][v] = 0ull;

    for (int s = 0; s < GNS; ++s) {
        const float* xp = x + ((size_t)b * NN + (size_t)c * GCH + (size_t)s * GSUB) * DD;
        __syncthreads();
        for (int idx = tid; idx < GSUB * DD; idx += 256) {
            int r = idx / DD, col = idx - r * DD;
            xs[r * 68 + col] = xp[idx];
        }
        __syncthreads();

#pragma unroll 8
        for (int k = 0; k < GSUB; ++k) {
            const float* row = xs + k * 68;
            const ull* xd = (const ull*)row;
            ull b0 = xd[p0], b1 = xd[p1], b2 = xd[p2];
#pragma unroll
            for (int u = 0; u < 5; ++u) {
                ull ad = pack2(row[iv[u]]);
                acc[u][0] = fma2(ad, b0, acc[u][0]);
                acc[u][1] = fma2(ad, b1, acc[u][1]);
                acc[u][2] = fma2(ad, b2, acc[u][2]);
            }
        }
    }

    float* gp = g_Gpart + (size_t)(b * NGC + c) * DSQ;
    const int pv[3] = {p0, p1, p2};
#pragma unroll
    for (int u = 0; u < 5; ++u) {
        int i = ty + 16 * u;
        if (i >= DD) continue;
#pragma unroll
        for (int v = 0; v < 3; ++v) {
            int j0 = 2 * pv[v];
            float lo, hi;
            unpack2(acc[u][v], lo, hi);
            if (j0     < DD) gp[i * DD + j0]     = lo;
            if (j0 + 1 < DD) gp[i * DD + j0 + 1] = hi;
        }
    }
}

// ---------------------------------------------------------------------------
// Kernel 2: mid chain with fused partial-Gram reduction. grid (3, 32).
// Block (t,b): rows [32t, 32t+32) through phases:
//   phase 0: A[i][j] = sum_h Wq[h][i]*Wk[h][j]
//   (B2 <- G = sum of 16 partials, fused reduce)
//   phase 1: T = A_tile * G;  phase 2: M = T_tile * Wv^T -> g_M
// ---------------------------------------------------------------------------
__global__ void __launch_bounds__(256) k_mid3(const float* __restrict__ Wq,
                                              const float* __restrict__ Wk,
                                              const float* __restrict__ Wv) {
    __shared__ __align__(16) float B1[DD * 68];
    __shared__ __align__(16) float B2[DD * 68];
    __shared__ __align__(16) float B3[32 * 68];

    const int b = blockIdx.y, t = blockIdx.x;
    const int tid = threadIdx.x;
    const int ty = tid >> 4, tx = tid & 15;
    const int p0 = tx, p1 = 16 + tx, p2 = (tx == 0) ? 32 : 33;
    const int pv[3] = {p0, p1, p2};
    const int i0 = t * 32;

    int iv[2];
#pragma unroll
    for (int u = 0; u < 2; ++u) {
        int i = i0 + ty + 16 * u;
        iv[u] = (i < DD) ? i : (DD - 1);
    }

    for (int idx = tid; idx < HH * DD; idx += 256) {
        int h = idx / DD, i = idx - h * DD;
        B1[h * 68 + i] = Wq[idx];
        B2[h * 68 + i] = Wk[idx];
    }
    __syncthreads();

    // phase 0: A-tile
    {
        ull acc[2][3];
#pragma unroll
        for (int u = 0; u < 2; ++u)
#pragma unroll
            for (int v = 0; v < 3; ++v) acc[u][v] = 0ull;
#pragma unroll 8
        for (int h = 0; h < HH; ++h) {
            const ull* kr = (const ull*)(B2 + h * 68);
            ull b0 = kr[p0], b1 = kr[p1], b2 = kr[p2];
            const float* qr = B1 + h * 68;
#pragma unroll
            for (int u = 0; u < 2; ++u) {
                ull ad = pack2(qr[iv[u]]);
                acc[u][0] = fma2(ad, b0, acc[u][0]);
                acc[u][1] = fma2(ad, b1, acc[u][1]);
                acc[u][2] = fma2(ad, b2, acc[u][2]);
            }
        }
        __syncthreads();
#pragma unroll
        for (int u = 0; u < 2; ++u) {
            ull* ap = (ull*)(B3 + (ty + 16 * u) * 68);
#pragma unroll
            for (int v = 0; v < 3; ++v) ap[pv[v]] = acc[u][v];
        }
    }
    // restage B2 <- G_b (fused 16-way partial reduction)
    {
        const float* gp = g_Gpart + (size_t)b * NGC * DSQ;
        for (int idx = tid; idx < DSQ; idx += 256) {
            float s0 = 0.f, s1 = 0.f, s2 = 0.f, s3 = 0.f;
#pragma unroll
            for (int c = 0; c < NGC; c += 4) {
                s0 += gp[(c + 0) * DSQ + idx];
                s1 += gp[(c + 1) * DSQ + idx];
                s2 += gp[(c + 2) * DSQ + idx];
                s3 += gp[(c + 3) * DSQ + idx];
            }
            int k = idx / DD, j = idx - k * DD;
            B2[k * 68 + j] = (s0 + s1) + (s2 + s3);
        }
    }
    __syncthreads();

    // phase 1: T-tile = A-tile * G
    ull accT[2][3];
#pragma unroll
    for (int u = 0; u < 2; ++u)
#pragma unroll
        for (int v = 0; v < 3; ++v) accT[u][v] = 0ull;
#pragma unroll 5
    for (int k = 0; k < DD; ++k) {
        const ull* gr = (const ull*)(B2 + k * 68);
        ull b0 = gr[p0], b1 = gr[p1], b2 = gr[p2];
#pragma unroll
        for (int u = 0; u < 2; ++u) {
            ull ad = pack2(B3[(ty + 16 * u) * 68 + k]);
            accT[u][0] = fma2(ad, b0, accT[u][0]);
            accT[u][1] = fma2(ad, b1, accT[u][1]);
            accT[u][2] = fma2(ad, b2, accT[u][2]);
        }
    }
    __syncthreads();

#pragma unroll
    for (int u = 0; u < 2; ++u) {
        ull* tp = (ull*)(B3 + (ty + 16 * u) * 68);
#pragma unroll
        for (int v = 0; v < 3; ++v) tp[pv[v]] = accT[u][v];
    }
    for (int idx = tid; idx < DSQ; idx += 256) {
        int j = idx / DD, k = idx - j * DD;
        B1[k * 68 + j] = Wv[idx];
    }
    __syncthreads();

    // phase 2: M-tile = T-tile * Wv^T
    {
        ull acc[2][3];
#pragma unroll
        for (int u = 0; u < 2; ++u)
#pragma unroll
            for (int v = 0; v < 3; ++v) acc[u][v] = 0ull;
#pragma unroll 5
        for (int k = 0; k < DD; ++k) {
            const ull* wr = (const ull*)(B1 + k * 68);
            ull b0 = wr[p0], b1 = wr[p1], b2 = wr[p2];
#pragma unroll
            for (int u = 0; u < 2; ++u) {
                ull ad = pack2(B3[(ty + 16 * u) * 68 + k]);
                acc[u][0] = fma2(ad, b0, acc[u][0]);
                acc[u][1] = fma2(ad, b1, acc[u][1]);
                acc[u][2] = fma2(ad, b2, acc[u][2]);
            }
        }
        float* Mb = g_M + (size_t)b * DSQ;
#pragma unroll
        for (int u = 0; u < 2; ++u) {
            int i = i0 + ty + 16 * u;
            if (i >= DD) continue;
#pragma unroll
            for (int v = 0; v < 3; ++v) {
                int j0 = 2 * pv[v];
                float lo, hi;
                unpack2(acc[u][v], lo, hi);
                if (j0     < DD) Mb[i * DD + j0]     = lo;
                if (j0 + 1 < DD) Mb[i * DD + j0 + 1] = hi;
            }
        }
    }
}

// ---------------------------------------------------------------------------
// Kernel 3: out_chunk = x_chunk * M_b. OCH=128, grid (16,32)=512.
// Dup'd M in smem (no pack movs) + x staged in TWO k-halves so smem stays at
// 51.5 KB -> 4 blocks/SM. Per k: 4 LDS.64(a) + 5 LDS.64(m bcast) + 20 FFMA2.
// Epilogue staged via smem (reuses Msd) then coalesced STG.
// ---------------------------------------------------------------------------
#define KHA 33
#define KHB 32

template<int K0, int KH>
__device__ __forceinline__ void out_half(const float* __restrict__ xp,
                                         float* xsT, const ull* mu,
                                         ull acc[4][5], const int jv[5],
                                         int tid, int tx) {
    for (int idx = tid; idx < OCH * KH; idx += 256) {
        int r = idx / KH, kh = idx - r * KH;
        xsT[kh * 130 + r] = xp[r * DD + K0 + kh];
    }
    __syncthreads();

    const ull* xu = (const ull*)xsT;   // 65 ulls per kh
#pragma unroll 3
    for (int kh = 0; kh < KH; ++kh) {
        const ull* xk = xu + kh * 65;
        ull a0 = xk[tx];
        ull a1 = xk[tx + 16];
        ull a2 = xk[tx + 32];
        ull a3 = xk[tx + 48];
        const ull* mk = mu + (K0 + kh) * 66;
#pragma unroll
        for (int v = 0; v < 5; ++v) {
            ull m = mk[jv[v]];
            acc[0][v] = fma2(a0, m, acc[0][v]);
            acc[1][v] = fma2(a1, m, acc[1][v]);
            acc[2][v] = fma2(a2, m, acc[2][v]);
            acc[3][v] = fma2(a3, m, acc[3][v]);
        }
    }
    __syncthreads();   // xsT free for next half / Msd free for epilogue
}

__global__ void __launch_bounds__(256, 4) k_out(const float* __restrict__ x,
                                                float* __restrict__ out) {
    extern __shared__ __align__(16) float smo[];
    float* Msd = smo;                 // 65*132 dup'd M; reused as osm[128*65]
    float* xsT = smo + DD * 132;      // 33*130 half-buffer of transposed x
    float* osm = Msd;

    const int b = blockIdx.y, c = blockIdx.x;
    const float* xp = x + ((size_t)b * NN + (size_t)c * OCH) * DD;
    float* op = out + ((size_t)b * NN + (size_t)c * OCH) * DD;
    const int tid = threadIdx.x;

    // stage dup'd M: one LDG + one STS.64 per element
    const float* Mg = g_M + (size_t)b * DSQ;
    for (int idx = tid; idx < DSQ; idx += 256) {
        int k = idx / DD, j = idx - k * DD;
        ((ull*)(Msd + k * 132))[j] = pack2(Mg[idx]);
    }
    // (first __syncthreads happens inside out_half after x staging)

    const int ty = tid >> 4, tx = tid & 15;
    int jv[5];
#pragma unroll
    for (int v = 0; v < 5; ++v) {
        int j = ty + 16 * v;
        jv[v] = (j < DD) ? j : (DD - 1);   // clamp loads; stores guarded by real j
    }

    ull acc[4][5];
#pragma unroll
    for (int u = 0; u < 4; ++u)
#pragma unroll
        for (int v = 0; v < 5; ++v) acc[u][v] = 0ull;

    const ull* mu = (const ull*)Msd;   // 66 ulls per k
    out_half<0,   KHA>(xp, xsT, mu, acc, jv, tid, tx);
    out_half<KHA, KHB>(xp, xsT, mu, acc, jv, tid, tx);

    // epilogue: stage into osm (overwrites Msd; sync already done), then STG
#pragma unroll
    for (int u = 0; u < 4; ++u) {
        int r0 = 2 * (tx + 16 * u);
#pragma unroll
        for (int v = 0; v < 5; ++v) {
            int j = ty + 16 * v;
            if (j < DD) {
                float lo, hi;
                unpack2(acc[u][v], lo, hi);
                osm[r0 * DD + j]       = lo;
                osm[(r0 + 1) * DD + j] = hi;
            }
        }
    }
    __syncthreads();

    for (int idx = tid; idx < OCH * DD; idx += 256)
        op[idx] = osm[idx];
}

// ---------------------------------------------------------------------------
extern "C" void kernel_launch(void* const* d_in, const int* in_sizes, int n_in,
                              void* d_out, int out_size) {
    const float* x  = (const float*)d_in[0];   // [32, 2048, 65]
    const float* Wq = (const float*)d_in[1];   // [64, 65]
    const float* Wk = (const float*)d_in[2];   // [64, 65]
    const float* Wv = (const float*)d_in[3];   // [65, 65]
    float* out = (float*)d_out;                // [32, 2048, 65]

    const int smem_out = (DD * 132 + KHA * 130) * 4;   // 34320 + 17160 = 51480 B
    cudaFuncSetAttribute(k_out, cudaFuncAttributeMaxDynamicSharedMemorySize, smem_out);

    k_gram<<<dim3(NGC, BB), 256>>>(x);
    k_mid3<<<dim3(3, BB), 256>>>(Wq, Wk, Wv);
    k_out<<<dim3(NOC, BB), 256, smem_out>>>(x, out);
}

// round 13
// speedup vs baseline: 1.0770x; 1.0770x over previous
#include <cuda_runtime.h>

// Problem constants
#define BB   32
#define NN   2048
#define DD   65
#define HH   64
#define DSQ  (DD*DD)        // 4225
#define GCH  64             // gram chunk rows per block
#define NGC  (NN/GCH)       // 32 partials per batch
#define OCH  128            // out chunk rows
#define NOC  (NN/OCH)       // 16

typedef unsigned long long ull;

// Scratch (no allocations allowed)
__device__ float g_Gpart[BB * NGC * DSQ];   // partial Gram matrices (~17.3 MB)
__device__ float g_G[BB * DSQ];             // reduced Gram
__device__ float g_M[BB * DSQ];             // M = A * G * Wv^T per batch

// ---- packed fp32x2 helpers ----
__device__ __forceinline__ ull pack2(float x) {
    ull d; unsigned u = __float_as_uint(x);
    asm("mov.b64 %0, {%1, %1};" : "=l"(d) : "r"(u));
    return d;
}
__device__ __forceinline__ ull fma2(ull a, ull b, ull c) {
    ull d;
    asm("fma.rn.f32x2 %0, %1, %2, %3;" : "=l"(d) : "l"(a), "l"(b), "l"(c));
    return d;
}
__device__ __forceinline__ void unpack2(ull d, float& lo, float& hi) {
    unsigned a, b;
    asm("mov.b64 {%0, %1}, %2;" : "=r"(a), "=r"(b) : "l"(d));
    lo = __uint_as_float(a); hi = __uint_as_float(b);
}

// ---------------------------------------------------------------------------
// Kernel 1 (R6 proven): partial Gram for a 64-row chunk. FFMA2, dup-buffer
// a-side (no pack movs): per k = 3 LDS.64(b) + 5 LDS.64(a-dup) + 15 FFMA2.
// grid (32, 32) = 1024 blocks, block 256, dynamic smem 58368 B.
// ---------------------------------------------------------------------------
__global__ void __launch_bounds__(256) k_gram(const float* __restrict__ x) {
    extern __shared__ __align__(16) float smg[];
    float* xs   = smg;               // 64*68  (b-side natural pairs)
    float* xdup = smg + GCH * 68;    // 64*160 (a-side duplicated pairs)

    const int b = blockIdx.y, c = blockIdx.x;
    const int tid = threadIdx.x;
    const float* xp = x + ((size_t)b * NN + (size_t)c * GCH) * DD;

    for (int idx = tid; idx < GCH * DD; idx += 256) {
        int r = idx / DD, col = idx - r * DD;
        float v = xp[idx];
        xs[r * 68 + col] = v;
        xdup[r * 160 + 2 * col]     = v;
        xdup[r * 160 + 2 * col + 1] = v;
    }
    __syncthreads();

    const int ty = tid >> 4, tx = tid & 15;
    const int p0 = tx, p1 = 16 + tx, p2 = (tx == 0) ? 32 : 33;  // pair 33 = pad (guarded)

    ull acc[5][3];
#pragma unroll
    for (int u = 0; u < 5; ++u)
#pragma unroll
        for (int v = 0; v < 3; ++v) acc[u][v] = 0ull;

#pragma unroll 4
    for (int k = 0; k < GCH; ++k) {
        const ull* xd = (const ull*)(xs + k * 68);
        const ull* ar = (const ull*)(xdup + k * 160);
        ull b0 = xd[p0], b1 = xd[p1], b2 = xd[p2];
#pragma unroll
        for (int u = 0; u < 5; ++u) {
            ull ad = ar[ty + 16 * u];
            acc[u][0] = fma2(ad, b0, acc[u][0]);
            acc[u][1] = fma2(ad, b1, acc[u][1]);
            acc[u][2] = fma2(ad, b2, acc[u][2]);
        }
    }

    float* gp = g_Gpart + (size_t)(b * NGC + c) * DSQ;
    const int pv[3] = {p0, p1, p2};
#pragma unroll
    for (int u = 0; u < 5; ++u) {
        int i = ty + 16 * u;
        if (i >= DD) continue;
#pragma unroll
        for (int v = 0; v < 3; ++v) {
            int j0 = 2 * pv[v];
            float lo, hi;
            unpack2(acc[u][v], lo, hi);
            if (j0     < DD) gp[i * DD + j0]     = lo;
            if (j0 + 1 < DD) gp[i * DD + j0 + 1] = hi;
        }
    }
}

// ---------------------------------------------------------------------------
// Kernel 2: reduce 32 partial Grams -> g_G.  grid (17, 32), block 256.
// ---------------------------------------------------------------------------
__global__ void k_reduce() {
    const int b = blockIdx.y;
    int idx = blockIdx.x * 256 + threadIdx.x;
    if (idx >= DSQ) return;
    const float* gp = g_Gpart + (size_t)b * NGC * DSQ + idx;
    float s0 = 0.f, s1 = 0.f, s2 = 0.f, s3 = 0.f;
#pragma unroll
    for (int c = 0; c < NGC; c += 4) {
        s0 += gp[(c + 0) * DSQ];
        s1 += gp[(c + 1) * DSQ];
        s2 += gp[(c + 2) * DSQ];
        s3 += gp[(c + 3) * DSQ];
    }
    g_G[b * DSQ + idx] = (s0 + s1) + (s2 + s3);
}

// ---------------------------------------------------------------------------
// Kernel 3 (R11 proven): mid chain, tiled 3 ways per batch. grid (3, 32).
// Block (t,b): rows [32t, 32t+32) through phases:
//   phase 0: A[i][j] = sum_h Wq[h][i]*Wk[h][j]
//   phase 1: T = A_tile * G;  phase 2: M = T_tile * Wv^T -> g_M
// ---------------------------------------------------------------------------
__global__ void __launch_bounds__(256) k_mid3(const float* __restrict__ Wq,
                                              const float* __restrict__ Wk,
                                              const float* __restrict__ Wv) {
    __shared__ __align__(16) float B1[DD * 68];
    __shared__ __align__(16) float B2[DD * 68];
    __shared__ __align__(16) float B3[32 * 68];

    const int b = blockIdx.y, t = blockIdx.x;
    const int tid = threadIdx.x;
    const int ty = tid >> 4, tx = tid & 15;
    const int p0 = tx, p1 = 16 + tx, p2 = (tx == 0) ? 32 : 33;
    const int pv[3] = {p0, p1, p2};
    const int i0 = t * 32;

    int iv[2];
#pragma unroll
    for (int u = 0; u < 2; ++u) {
        int i = i0 + ty + 16 * u;
        iv[u] = (i < DD) ? i : (DD - 1);
    }

    for (int idx = tid; idx < HH * DD; idx += 256) {
        int h = idx / DD, i = idx - h * DD;
        B1[h * 68 + i] = Wq[idx];
        B2[h * 68 + i] = Wk[idx];
    }
    __syncthreads();

    // phase 0: A-tile
    {
        ull acc[2][3];
#pragma unroll
        for (int u = 0; u < 2; ++u)
#pragma unroll
            for (int v = 0; v < 3; ++v) acc[u][v] = 0ull;
#pragma unroll 8
        for (int h = 0; h < HH; ++h) {
            const ull* kr = (const ull*)(B2 + h * 68);
            ull b0 = kr[p0], b1 = kr[p1], b2 = kr[p2];
            const float* qr = B1 + h * 68;
#pragma unroll
            for (int u = 0; u < 2; ++u) {
                ull ad = pack2(qr[iv[u]]);
                acc[u][0] = fma2(ad, b0, acc[u][0]);
                acc[u][1] = fma2(ad, b1, acc[u][1]);
                acc[u][2] = fma2(ad, b2, acc[u][2]);
            }
        }
        __syncthreads();
#pragma unroll
        for (int u = 0; u < 2; ++u) {
            ull* ap = (ull*)(B3 + (ty + 16 * u) * 68);
#pragma unroll
            for (int v = 0; v < 3; ++v) ap[pv[v]] = acc[u][v];
        }
    }
    // restage B2 <- G_b
    for (int idx = tid; idx < DSQ; idx += 256) {
        int k = idx / DD, j = idx - k * DD;
        B2[k * 68 + j] = g_G[(size_t)b * DSQ + idx];
    }
    __syncthreads();

    // phase 1: T-tile = A-tile * G
    ull accT[2][3];
#pragma unroll
    for (int u = 0; u < 2; ++u)
#pragma unroll
        for (int v = 0; v < 3; ++v) accT[u][v] = 0ull;
#pragma unroll 5
    for (int k = 0; k < DD; ++k) {
        const ull* gr = (const ull*)(B2 + k * 68);
        ull b0 = gr[p0], b1 = gr[p1], b2 = gr[p2];
#pragma unroll
        for (int u = 0; u < 2; ++u) {
            ull ad = pack2(B3[(ty + 16 * u) * 68 + k]);
            accT[u][0] = fma2(ad, b0, accT[u][0]);
            accT[u][1] = fma2(ad, b1, accT[u][1]);
            accT[u][2] = fma2(ad, b2, accT[u][2]);
        }
    }
    __syncthreads();

#pragma unroll
    for (int u = 0; u < 2; ++u) {
        ull* tp = (ull*)(B3 + (ty + 16 * u) * 68);
#pragma unroll
        for (int v = 0; v < 3; ++v) tp[pv[v]] = accT[u][v];
    }
    for (int idx = tid; idx < DSQ; idx += 256) {
        int j = idx / DD, k = idx - j * DD;
        B1[k * 68 + j] = Wv[idx];
    }
    __syncthreads();

    // phase 2: M-tile = T-tile * Wv^T
    {
        ull acc[2][3];
#pragma unroll
        for (int u = 0; u < 2; ++u)
#pragma unroll
            for (int v = 0; v < 3; ++v) acc[u][v] = 0ull;
#pragma unroll 5
        for (int k = 0; k < DD; ++k) {
            const ull* wr = (const ull*)(B1 + k * 68);
            ull b0 = wr[p0], b1 = wr[p1], b2 = wr[p2];
#pragma unroll
            for (int u = 0; u < 2; ++u) {
                ull ad = pack2(B3[(ty + 16 * u) * 68 + k]);
                acc[u][0] = fma2(ad, b0, acc[u][0]);
                acc[u][1] = fma2(ad, b1, acc[u][1]);
                acc[u][2] = fma2(ad, b2, acc[u][2]);
            }
        }
        float* Mb = g_M + (size_t)b * DSQ;
#pragma unroll
        for (int u = 0; u < 2; ++u) {
            int i = i0 + ty + 16 * u;
            if (i >= DD) continue;
#pragma unroll
            for (int v = 0; v < 3; ++v) {
                int j0 = 2 * pv[v];
                float lo, hi;
                unpack2(acc[u][v], lo, hi);
                if (j0     < DD) Mb[i * DD + j0]     = lo;
                if (j0 + 1 < DD) Mb[i * DD + j0 + 1] = hi;
            }
        }
    }
}

// ---------------------------------------------------------------------------
// Kernel 4 (R8/R11 proven): out_chunk = x_chunk * M_b, OCH=128, grid (16,32).
// acc pairs = output rows; a = natural x row-pairs from xsT[k][r] (pitch 130);
// b = pack2(M[k][j]) one column at a time. Epilogue staged via smem.
// ---------------------------------------------------------------------------
__global__ void __launch_bounds__(256, 4) k_out(const float* __restrict__ x,
                                                float* __restrict__ out) {
    extern __shared__ __align__(16) float smo[];
    float* Ms  = smo;                 // 65*66
    float* xsT = smo + DD * 66;       // 65*130 transposed x; reused as osm[128*65]
    float* osm = xsT;

    const int b = blockIdx.y, c = blockIdx.x;
    const float* xp = x + ((size_t)b * NN + (size_t)c * OCH) * DD;
    float* op = out + ((size_t)b * NN + (size_t)c * OCH) * DD;
    const int tid = threadIdx.x;

    const float* Mg = g_M + (size_t)b * DSQ;
    for (int idx = tid; idx < DSQ; idx += 256) {
        int k = idx / DD, j = idx - k * DD;
        Ms[k * 66 + j] = Mg[idx];
    }
    for (int idx = tid; idx < OCH * DD; idx += 256) {
        int r = idx / DD, k = idx - r * DD;
        xsT[k * 130 + r] = xp[idx];
    }
    __syncthreads();

    const int ty = tid >> 4, tx = tid & 15;
    int jv[5];
#pragma unroll
    for (int v = 0; v < 5; ++v) {
        int j = ty + 16 * v;
        jv[v] = (j < DD) ? j : (DD - 1);   // clamp loads; stores guarded by real j
    }

    ull acc[4][5];
#pragma unroll
    for (int u = 0; u < 4; ++u)
#pragma unroll
        for (int v = 0; v < 5; ++v) acc[u][v] = 0ull;

    const ull* xu = (const ull*)xsT;   // pitch 65 ulls per k
#pragma unroll 5
    for (int k = 0; k < DD; ++k) {
        const ull* xk = xu + k * 65;
        ull a0 = xk[tx];
        ull a1 = xk[tx + 16];
        ull a2 = xk[tx + 32];
        ull a3 = xk[tx + 48];
        const float* mk = Ms + k * 66;
#pragma unroll
        for (int v = 0; v < 5; ++v) {
            ull m = pack2(mk[jv[v]]);
            acc[0][v] = fma2(a0, m, acc[0][v]);
            acc[1][v] = fma2(a1, m, acc[1][v]);
            acc[2][v] = fma2(a2, m, acc[2][v]);
            acc[3][v] = fma2(a3, m, acc[3][v]);
        }
    }

    __syncthreads();   // all xsT reads done before osm overwrite

#pragma unroll
    for (int u = 0; u < 4; ++u) {
        int r0 = 2 * (tx + 16 * u);
#pragma unroll
        for (int v = 0; v < 5; ++v) {
            int j = ty + 16 * v;
            if (j < DD) {
                float lo, hi;
                unpack2(acc[u][v], lo, hi);
                osm[r0 * DD + j]       = lo;
                osm[(r0 + 1) * DD + j] = hi;
            }
        }
    }
    __syncthreads();

    for (int idx = tid; idx < OCH * DD; idx += 256)
        op[idx] = osm[idx];
}

// ---------------------------------------------------------------------------
extern "C" void kernel_launch(void* const* d_in, const int* in_sizes, int n_in,
                              void* d_out, int out_size) {
    const float* x  = (const float*)d_in[0];   // [32, 2048, 65]
    const float* Wq = (const float*)d_in[1];   // [64, 65]
    const float* Wk = (const float*)d_in[2];   // [64, 65]
    const float* Wv = (const float*)d_in[3];   // [65, 65]
    float* out = (float*)d_out;                // [32, 2048, 65]

    const int smem_gram = (GCH * 68 + GCH * 160) * 4;   // 58368 B
    const int smem_out  = (DD * 66 + DD * 130) * 4;     // 50960 B
    cudaFuncSetAttribute(k_gram, cudaFuncAttributeMaxDynamicSharedMemorySize, smem_gram);
    cudaFuncSetAttribute(k_out,  cudaFuncAttributeMaxDynamicSharedMemorySize, smem_out);

    k_gram<<<dim3(NGC, BB), 256, smem_gram>>>(x);
    k_reduce<<<dim3(17, BB), 256>>>();
    k_mid3<<<dim3(3, BB), 256>>>(Wq, Wk, Wv);
    k_out<<<dim3(NOC, BB), 256, smem_out>>>(x, out);
}